// round 1
// baseline (speedup 1.0000x reference)
#include <cuda_runtime.h>

namespace {

constexpr int BATCH   = 4;
constexpr int NIN     = 1024;
constexpr int NOUT    = 1024;
constexpr int CH      = 8;    // density + 7 raw channels
constexpr int OC      = 16;
constexpr int OPB     = 32;   // outputs per block
constexpr int THREADS = 256;
constexpr int WARPS   = THREADS / 32;       // 8
constexpr int IPW     = NIN / WARPS;        // 128 context points per warp

__device__ __forceinline__ float ex2_approx(float x) {
    float y;
    asm("ex2.approx.f32 %0, %1;" : "=f"(y) : "f"(x));
    return y;
}

__global__ __launch_bounds__(THREADS, 1)
void convdeepset_kernel(const float* __restrict__ cx,     // [B, NIN, 1]
                        const float* __restrict__ cy,     // [B, NIN, 7]
                        const float* __restrict__ t,      // [B, NOUT, 1]
                        const float* __restrict__ sigma,  // [8]
                        const float* __restrict__ W,      // [8, 16]
                        const float* __restrict__ bias,   // [16]
                        float* __restrict__ out)          // [B, NOUT, 16]
{
    __shared__ float sx[NIN];                     // 4 KB
    __shared__ float sy[NIN][CH];                 // 32 KB (density + 7 ch)
    __shared__ float spart[WARPS][OPB][CH];       // 8 KB partials (reused for agg2)
    __shared__ float sagg[OPB][CH];
    __shared__ float sbeta[CH];
    __shared__ int   suni;

    const int blocksPerBatch = NOUT / OPB;        // 32
    const int b     = blockIdx.x / blocksPerBatch;
    const int otile = blockIdx.x % blocksPerBatch;
    const int tid   = threadIdx.x;
    const int warp  = tid >> 5;
    const int lane  = tid & 31;

    // Per-channel exponent: exp(-0.5*d2/s^2) = exp2(beta * d2),
    // beta = -0.5*log2(e)/s^2, s = exp(sigma)
    if (tid < CH) {
        float s = expf(sigma[tid]);
        sbeta[tid] = -0.5f * 1.4426950408889634f / (s * s);
    }

    // Stage context x and y (with density channel) into shared
    for (int i = tid; i < NIN; i += THREADS) sx[i] = cx[b * NIN + i];
    for (int idx = tid; idx < NIN * CH; idx += THREADS) {
        int i = idx >> 3, c = idx & 7;
        sy[i][c] = (c == 0) ? 1.0f : cy[(b * NIN + i) * (CH - 1) + (c - 1)];
    }
    __syncthreads();

    if (tid == 0) {
        int u = 1;
        #pragma unroll
        for (int c = 1; c < CH; c++) u &= (sbeta[c] == sbeta[0]);
        suni = u;
    }
    __syncthreads();

    // Each lane owns one output; each warp owns a 128-wide slice of i.
    const int   o   = otile * OPB + lane;
    const float t_o = t[b * NOUT + o];

    float acc[CH];
    #pragma unroll
    for (int c = 0; c < CH; c++) acc[c] = 0.0f;

    const int i0 = warp * IPW;

    if (suni) {
        // Fast path: all channels share the same length scale -> one EX2/pair
        const float beta0 = sbeta[0];
        #pragma unroll 4
        for (int i = i0; i < i0 + IPW; i++) {
            float d = sx[i] - t_o;
            float w = ex2_approx(beta0 * (d * d));
            float4 y0 = *reinterpret_cast<const float4*>(&sy[i][0]);
            float4 y1 = *reinterpret_cast<const float4*>(&sy[i][4]);
            acc[0] += y0.x * w;  acc[1] += y0.y * w;
            acc[2] += y0.z * w;  acc[3] += y0.w * w;
            acc[4] += y1.x * w;  acc[5] += y1.y * w;
            acc[6] += y1.z * w;  acc[7] += y1.w * w;
        }
    } else {
        // General path: per-channel exponent
        float betas[CH];
        #pragma unroll
        for (int c = 0; c < CH; c++) betas[c] = sbeta[c];
        #pragma unroll 2
        for (int i = i0; i < i0 + IPW; i++) {
            float d = sx[i] - t_o;
            float u = d * d;
            float4 y0 = *reinterpret_cast<const float4*>(&sy[i][0]);
            float4 y1 = *reinterpret_cast<const float4*>(&sy[i][4]);
            acc[0] += y0.x * ex2_approx(betas[0] * u);
            acc[1] += y0.y * ex2_approx(betas[1] * u);
            acc[2] += y0.z * ex2_approx(betas[2] * u);
            acc[3] += y0.w * ex2_approx(betas[3] * u);
            acc[4] += y1.x * ex2_approx(betas[4] * u);
            acc[5] += y1.y * ex2_approx(betas[5] * u);
            acc[6] += y1.z * ex2_approx(betas[6] * u);
            acc[7] += y1.w * ex2_approx(betas[7] * u);
        }
    }

    // Write per-warp partials
    #pragma unroll
    for (int c = 0; c < CH; c += 4) {
        float4 v = make_float4(acc[c], acc[c + 1], acc[c + 2], acc[c + 3]);
        *reinterpret_cast<float4*>(&spart[warp][lane][c]) = v;
    }
    __syncthreads();

    // Cross-warp reduction: thread -> (o_local = tid/8, c = tid%8)
    {
        int o_l = tid >> 3, c = tid & 7;
        float s = 0.0f;
        #pragma unroll
        for (int w2 = 0; w2 < WARPS; w2++) s += spart[w2][o_l][c];
        sagg[o_l][c] = s;
    }
    __syncthreads();

    // Normalize: agg2 = [den, conv/(den+1e-8)]  (reuse spart[0] as agg2)
    {
        int o_l = tid >> 3, c = tid & 7;
        float den = sagg[o_l][0];
        float v = (c == 0) ? den : sagg[o_l][c] / (den + 1e-8f);
        spart[0][o_l][c] = v;
    }
    __syncthreads();

    // Epilogue: out[o][k] = b[k] + sum_c agg2[o][c] * W[c][k]
    for (int j = tid; j < OPB * OC; j += THREADS) {
        int o_l = j >> 4, k = j & 15;
        float v = __ldg(&bias[k]);
        #pragma unroll
        for (int c = 0; c < CH; c++) v += spart[0][o_l][c] * __ldg(&W[c * OC + k]);
        out[(b * NOUT + otile * OPB + o_l) * OC + k] = v;
    }
}

} // namespace

extern "C" void kernel_launch(void* const* d_in, const int* in_sizes, int n_in,
                              void* d_out, int out_size) {
    const float* cx = (const float*)d_in[0];  // context_x
    const float* cy = (const float*)d_in[1];  // context_y
    const float* t  = (const float*)d_in[2];  // t
    const float* sg = (const float*)d_in[3];  // sigma
    const float* W  = (const float*)d_in[4];  // W
    const float* bi = (const float*)d_in[5];  // b
    float* out = (float*)d_out;

    dim3 grid(BATCH * (NOUT / OPB));          // 128 blocks
    convdeepset_kernel<<<grid, THREADS>>>(cx, cy, t, sg, W, bi, out);
}